// round 12
// baseline (speedup 1.0000x reference)
#include <cuda_runtime.h>
#include <cuda_fp16.h>

#define MBATCH 32
#define ET 4
#define NN 512
#define IN0 64
#define HID 128
#define ROWS (MBATCH*NN)      /* 16384 */
#define MAXNBR 64
#define KP0 352               /* pad(5*64+4, 32)  */
#define KP12 672              /* pad(5*128+4, 32) */
#define EPSV 1e-5f

/* transposed-weight column offsets inside g_Wt[128][WTCOLS] */
#define WT0 0
#define WT1 352
#define WT2 1024
#define WT3 1696
#define WT4 1824
#define WTCOLS 1952

/* prep2 sub-grid block counts */
#define NB_SSUM   ((MBATCH*ET*NN)/256)            /* 256  */
#define NB_STAGE0 ((MBATCH*NN*IN0/4)/256)         /* 1024 */
#define NB_WPREP  ((HID*WTCOLS + 255)/256)        /* 976  */

/* ---------------- static device scratch (no allocation) ---------------- */
__device__ float          g_inv[MBATCH*NN];
__device__ float          g_ssum[MBATCH*ET*NN];
__device__ __align__(16) unsigned short g_nbr[MBATCH*ET*NN*MAXNBR];  /* node idx */
__device__ int            g_cnt[MBATCH*ET*NN];              // clamped
__device__ int            g_cntfull[MBATCH*ET*NN];          // exact
__device__ __align__(16) __half g_A[ROWS*KP12];             // 22 MB
__device__ __align__(16) __half g_Wt[HID*WTCOLS];           // 0.5 MB
__device__ __align__(16) float  g_pre[ROWS*HID];            // 8.4 MB
__device__ __align__(16) __half g_hh[ROWS*HID];             // post-BN act, fp16
__device__ __align__(16) __half g_h16[ROWS*HID];            // inv-scaled act
__device__ __align__(16) __half g_x16[MBATCH*NN*IN0];       // inv-scaled x
__device__ float          g_bnsum[4*NN];
__device__ float          g_bnsq[4*NN];

/* ------------- 1) CSR build: one warp per (b,e,n) row, float4 reads ----- */
__global__ void k_csr(const float* __restrict__ adj) {
    int row  = blockIdx.x * 8 + (threadIdx.x >> 5);
    int lane = threadIdx.x & 31;
    int n    = row & (NN - 1);
    const float4* p = (const float4*)(adj + (size_t)row * NN);
    unsigned short* out = g_nbr + (size_t)row * MAXNBR;
    int cnt = 0;
    for (int it = 0; it < NN / 128; it++) {
        float4 v = p[it * 32 + lane];
        int mb = (it * 32 + lane) * 4;
        float vc[4] = {v.x, v.y, v.z, v.w};
#pragma unroll
        for (int c = 0; c < 4; c++) {
            bool pr = (vc[c] != 0.f) && (mb + c != n);
            unsigned msk = __ballot_sync(0xffffffffu, pr);
            if (pr) {
                int pos = cnt + __popc(msk & ((1u << lane) - 1u));
                if (pos < MAXNBR) out[pos] = (unsigned short)(mb + c);
            }
            cnt += __popc(msk);
        }
    }
    if (lane == 0) {
        g_cnt[row]     = cnt < MAXNBR ? cnt : MAXNBR;
        g_cntfull[row] = cnt;
    }
}

/* ------------- 2) inv degree from exact counts (adj symmetric, 0/1) ---- */
__global__ void k_deg() {
    int i = blockIdx.x * 256 + threadIdx.x;
    int b = i >> 9, m = i & 511;
    int d = 0;
#pragma unroll
    for (int e = 0; e < ET; e++) d += g_cntfull[((b * ET + e) << 9) + m];
    g_inv[i] = d > 0 ? 1.f / (float)d : 0.f;
}

/* ------------- 3) fused prep: ssum | stage0 | wprep (block dispatch) --- */
__global__ void k_prep2(const float* __restrict__ x,
    const float* __restrict__ ws0, const float* __restrict__ we0, const float* __restrict__ be0,
    const float* __restrict__ ws1, const float* __restrict__ we1, const float* __restrict__ be1,
    const float* __restrict__ ws2, const float* __restrict__ we2, const float* __restrict__ be2,
    const float* __restrict__ w1,  const float* __restrict__ w2) {
    int blk = blockIdx.x;
    if (blk < NB_SSUM) {
        int lidx = blk * 256 + threadIdx.x;
        int b = lidx >> 11;
        int cnt = g_cnt[lidx];
        const unsigned short* nb = g_nbr + (size_t)lidx * MAXNBR;
        const float* invb = g_inv + b * NN;
        float s = 0.f;
        for (int i = 0; i < cnt; i++) s += invb[nb[i]];
        g_ssum[lidx] = s;
        if (lidx < 4 * NN) { g_bnsum[lidx] = 0.f; g_bnsq[lidx] = 0.f; }
        return;
    }
    blk -= NB_SSUM;
    if (blk < NB_STAGE0) {
        int i4 = blk * 256 + threadIdx.x;
        float4 v = ((const float4*)x)[i4];
        int r = i4 >> 4;
        float w = g_inv[r];
        __half2 h0 = __floats2half2_rn(w * v.x, w * v.y);
        __half2 h1 = __floats2half2_rn(w * v.z, w * v.w);
        uint2 u; u.x = *(unsigned*)&h0; u.y = *(unsigned*)&h1;
        ((uint2*)g_x16)[i4] = u;
        return;
    }
    blk -= NB_STAGE0;
    {
        int idx = blk * 256 + threadIdx.x;
        if (idx >= HID * WTCOLS) return;
        int o = idx / WTCOLS, k = idx - o * WTCOLS;
        float v = 0.f;
        if (k < WT1) {
            int kk = k;
            if (kk < 64)       v = ws0[kk * HID + o];
            else if (kk < 320) { int e = (kk - 64) >> 6, j = (kk - 64) & 63;
                                 v = we0[j * (HID * ET) + o * ET + e]; }
            else if (kk < 324)   v = be0[o * ET + (kk - 320)];
        } else if (k < WT2) {
            int kk = k - WT1;
            if (kk < 128)      v = ws1[kk * HID + o];
            else if (kk < 640) { int e = (kk - 128) >> 7, j = (kk - 128) & 127;
                                 v = we1[j * (HID * ET) + o * ET + e]; }
            else if (kk < 644)   v = be1[o * ET + (kk - 640)];
        } else if (k < WT3) {
            int kk = k - WT2;
            if (kk < 128)      v = ws2[kk * HID + o];
            else if (kk < 640) { int e = (kk - 128) >> 7, j = (kk - 128) & 127;
                                 v = we2[j * (HID * ET) + o * ET + e]; }
            else if (kk < 644)   v = be2[o * ET + (kk - 640)];
        } else if (k < WT4) {
            v = w1[(k - WT3) * HID + o];
        } else {
            v = w2[(k - WT4) * HID + o];
        }
        g_Wt[o * WTCOLS + k] = __float2half_rn(v);
    }
}

/* ------------- 4) sparse aggregation: u16 idx + fp16 tree-sum ---------- */
template<int IN>
__global__ void __launch_bounds__(128, 12) k_agg(const float* __restrict__ x0, int KP) {
    constexpr int VEC = IN / 32;   // 4 for IN=128, 2 for IN=64
    const __half* __restrict__ h16 = (IN == IN0) ? (const __half*)g_x16
                                                 : (const __half*)g_h16;
    int r = blockIdx.x, b = r >> 9, n = r & 511;
    int warp = threadIdx.x >> 5, lane = threadIdx.x & 31;
    __half* Arow = g_A + (size_t)r * KP;

    if (warp == 0) {   /* self-feature copy */
        if (IN == IN0) {
            float2 v = *(const float2*)(x0 + (size_t)r * IN + lane * 2);
            *(__half2*)(Arow + lane * 2) = __floats2half2_rn(v.x, v.y);
        } else {
            *(uint2*)(Arow + lane * 4) =
                *(const uint2*)((const __half*)g_hh + (size_t)r * IN + lane * 4);
        }
    }
    if (warp == 1) {   /* s-values + zero-pad tail */
        if (lane < ET)
            Arow[5 * IN + lane] = __float2half_rn(g_ssum[((b * ET + lane) << 9) + n]);
        for (int k = 5 * IN + 4 + lane; k < KP; k += 32) Arow[k] = __half(0.f);
    }

    int e = warp;
    int lidx = ((b * ET + e) << 9) + n;
    int cnt = g_cnt[lidx];
    const unsigned short* nb = g_nbr + (size_t)lidx * MAXNBR;
    const uint2* nbq = (const uint2*)nb;      /* 16 groups of 4 u16 */
    const __half* hb = h16 + (size_t)b * NN * IN + lane * VEC;

    float acc[VEC];
#pragma unroll
    for (int c = 0; c < VEC; c++) acc[c] = 0.f;

    int i = 0;
    if (cnt >= 4) {
        uint2 qc = nbq[0];                    /* index prefetch, distance 1 */
        for (; i + 4 <= cnt; i += 4) {
            int g = (i >> 2) + 1;
            uint2 qn = nbq[g < 16 ? g : 15];
            int m0 = qc.x & 0xffff, m1 = qc.x >> 16;
            int m2 = qc.y & 0xffff, m3 = qc.y >> 16;
            if (VEC == 4) {
                uint2 f0 = *(const uint2*)(hb + (size_t)m0 * IN);
                uint2 f1 = *(const uint2*)(hb + (size_t)m1 * IN);
                uint2 f2 = *(const uint2*)(hb + (size_t)m2 * IN);
                uint2 f3 = *(const uint2*)(hb + (size_t)m3 * IN);
                /* fp16 depth-2 tree per half2 column, one convert per batch */
                __half2 sx = __hadd2(__hadd2(*(__half2*)&f0.x, *(__half2*)&f1.x),
                                     __hadd2(*(__half2*)&f2.x, *(__half2*)&f3.x));
                __half2 sy = __hadd2(__hadd2(*(__half2*)&f0.y, *(__half2*)&f1.y),
                                     __hadd2(*(__half2*)&f2.y, *(__half2*)&f3.y));
                float2 a = __half22float2(sx);
                float2 bb2 = __half22float2(sy);
                acc[0] += a.x; acc[1] += a.y; acc[2] += bb2.x; acc[3] += bb2.y;
            } else {
                unsigned f0 = *(const unsigned*)(hb + (size_t)m0 * IN);
                unsigned f1 = *(const unsigned*)(hb + (size_t)m1 * IN);
                unsigned f2 = *(const unsigned*)(hb + (size_t)m2 * IN);
                unsigned f3 = *(const unsigned*)(hb + (size_t)m3 * IN);
                __half2 s = __hadd2(__hadd2(*(__half2*)&f0, *(__half2*)&f1),
                                    __hadd2(*(__half2*)&f2, *(__half2*)&f3));
                float2 a = __half22float2(s);
                acc[0] += a.x; acc[1] += a.y;
            }
            qc = qn;
        }
    }
    for (; i < cnt; i++) {
        int m = nb[i];
        if (VEC == 4) {
            uint2 f0 = *(const uint2*)(hb + (size_t)m * IN);
            float2 a = __half22float2(*(__half2*)&f0.x);
            float2 bb2 = __half22float2(*(__half2*)&f0.y);
            acc[0] += a.x; acc[1] += a.y; acc[2] += bb2.x; acc[3] += bb2.y;
        } else {
            unsigned f0 = *(const unsigned*)(hb + (size_t)m * IN);
            float2 a = __half22float2(*(__half2*)&f0);
            acc[0] += a.x; acc[1] += a.y;
        }
    }

    if (VEC == 4) {
        __half2 o0 = __floats2half2_rn(acc[0], acc[1]);
        __half2 o1 = __floats2half2_rn(acc[2], acc[3]);
        uint2 u; u.x = *(unsigned*)&o0; u.y = *(unsigned*)&o1;
        *(uint2*)(Arow + IN + e * IN + lane * 4) = u;
    } else {
        *(__half2*)(Arow + IN + e * IN + lane * 2) = __floats2half2_rn(acc[0], acc[1]);
    }
}

/* ------------- 5) FP16 tensor GEMM (m16n8k16, ldmatrix) + BN stats ----- */
#define SROW 40   /* smem row pitch in halfs (32 data + 8 pad) */

__device__ __forceinline__ unsigned smaddr(const void* p) {
    return (unsigned)__cvta_generic_to_shared(p);
}
__device__ __forceinline__ void cpasync16(unsigned s, const void* g) {
    asm volatile("cp.async.cg.shared.global [%0], [%1], 16;\n" :: "r"(s), "l"(g));
}
__device__ __forceinline__ void ldsm4(unsigned& r0, unsigned& r1, unsigned& r2,
                                      unsigned& r3, unsigned addr) {
    asm volatile("ldmatrix.sync.aligned.m8n8.x4.shared.b16 {%0,%1,%2,%3}, [%4];\n"
                 : "=r"(r0), "=r"(r1), "=r"(r2), "=r"(r3) : "r"(addr));
}

__global__ void __launch_bounds__(256) k_gemm(int KP, const float* __restrict__ bias,
                                              int srcH, float* __restrict__ Cout,
                                              int wofs, int sb) {
    const __half* A = srcH ? (const __half*)g_hh : (const __half*)g_A;
    float* C = Cout ? Cout : (float*)g_pre;

    __shared__ __half sA[2][128 * SROW];
    __shared__ __half sB[2][128 * SROW];
    const unsigned BUFB = 128 * SROW * 2;        /* bytes per buffer */

    int tid = threadIdx.x;
    int lane = tid & 31, warp = tid >> 5;
    int wm = (warp >> 1) * 32, wn = (warp & 1) * 64;
    int grp = lane >> 2, qid = lane & 3;
    int rowbase = blockIdx.x * 128;
    int KB = KP >> 5;

    unsigned aBase = smaddr(&sA[0][0]);
    unsigned bBase = smaddr(&sB[0][0]);
    int l7 = lane & 7, lb3 = (lane >> 3) & 1, lb4 = lane >> 4;
    unsigned aOff[2], bOff[4];
#pragma unroll
    for (int mi = 0; mi < 2; mi++)
        aOff[mi] = ((wm + mi * 16 + lb3 * 8 + l7) * SROW + lb4 * 8) * 2;
#pragma unroll
    for (int p = 0; p < 4; p++)
        bOff[p] = ((wn + p * 16 + lb4 * 8 + l7) * SROW + lb3 * 8) * 2;

    float acc[2][8][4];
#pragma unroll
    for (int a = 0; a < 2; a++)
#pragma unroll
        for (int bq = 0; bq < 8; bq++)
#pragma unroll
            for (int c = 0; c < 4; c++) acc[a][bq][c] = 0.f;

    auto issue = [&](int kb, int buf) {
        int kof = kb * 32;
#pragma unroll
        for (int i = 0; i < 2; i++) {
            int c = tid + i * 256, row = c >> 2, q = c & 3;
            cpasync16(smaddr(&sA[buf][row * SROW + q * 8]),
                      A + (size_t)(rowbase + row) * KP + kof + q * 8);
            cpasync16(smaddr(&sB[buf][row * SROW + q * 8]),
                      (const __half*)g_Wt + (size_t)row * WTCOLS + wofs + kof + q * 8);
        }
        asm volatile("cp.async.commit_group;\n" ::);
    };

    issue(0, 0);
    for (int kb = 0; kb < KB; kb++) {
        int buf = kb & 1;
        if (kb + 1 < KB) {
            issue(kb + 1, buf ^ 1);
            asm volatile("cp.async.wait_group 1;\n" ::);
        } else {
            asm volatile("cp.async.wait_group 0;\n" ::);
        }
        __syncthreads();

#pragma unroll
        for (int ks = 0; ks < 2; ks++) {
            unsigned kby = ks * 32 + buf * BUFB;
            unsigned bf[8][2];
#pragma unroll
            for (int p = 0; p < 4; p++)
                ldsm4(bf[2*p][0], bf[2*p][1], bf[2*p+1][0], bf[2*p+1][1],
                      bBase + bOff[p] + kby);
#pragma unroll
            for (int mi = 0; mi < 2; mi++) {
                unsigned a0, a1, a2, a3;
                ldsm4(a0, a1, a2, a3, aBase + aOff[mi] + kby);
#pragma unroll
                for (int ni = 0; ni < 8; ni++) {
                    asm volatile(
                        "mma.sync.aligned.m16n8k16.row.col.f32.f16.f16.f32 "
                        "{%0,%1,%2,%3}, {%4,%5,%6,%7}, {%8,%9}, {%0,%1,%2,%3};\n"
                        : "+f"(acc[mi][ni][0]), "+f"(acc[mi][ni][1]),
                          "+f"(acc[mi][ni][2]), "+f"(acc[mi][ni][3])
                        : "r"(a0), "r"(a1), "r"(a2), "r"(a3),
                          "r"(bf[ni][0]), "r"(bf[ni][1]));
                }
            }
        }
        __syncthreads();
    }

    /* epilogue: +bias, store, per-row BN partial sums */
    float rs[2][2] = {{0.f,0.f},{0.f,0.f}};
    float rq[2][2] = {{0.f,0.f},{0.f,0.f}};
#pragma unroll
    for (int mi = 0; mi < 2; mi++) {
        int row = rowbase + wm + mi * 16 + grp;
#pragma unroll
        for (int ni = 0; ni < 8; ni++) {
            int col = wn + ni * 8 + qid * 2;
            float b0 = bias[col], b1 = bias[col + 1];
            float v0 = acc[mi][ni][0] + b0, v1 = acc[mi][ni][1] + b1;
            float v2 = acc[mi][ni][2] + b0, v3 = acc[mi][ni][3] + b1;
            C[(size_t)row * HID + col]           = v0;
            C[(size_t)row * HID + col + 1]       = v1;
            C[(size_t)(row + 8) * HID + col]     = v2;
            C[(size_t)(row + 8) * HID + col + 1] = v3;
            rs[mi][0] += v0 + v1; rq[mi][0] += v0 * v0 + v1 * v1;
            rs[mi][1] += v2 + v3; rq[mi][1] += v2 * v2 + v3 * v3;
        }
    }
    if (sb >= 0) {
#pragma unroll
        for (int mi = 0; mi < 2; mi++)
#pragma unroll
            for (int rr = 0; rr < 2; rr++) {
                rs[mi][rr] += __shfl_xor_sync(0xffffffffu, rs[mi][rr], 1);
                rs[mi][rr] += __shfl_xor_sync(0xffffffffu, rs[mi][rr], 2);
                rq[mi][rr] += __shfl_xor_sync(0xffffffffu, rq[mi][rr], 1);
                rq[mi][rr] += __shfl_xor_sync(0xffffffffu, rq[mi][rr], 2);
            }
        if (qid == 0) {
#pragma unroll
            for (int mi = 0; mi < 2; mi++)
#pragma unroll
                for (int rr = 0; rr < 2; rr++) {
                    int row = rowbase + wm + mi * 16 + grp + rr * 8;
                    int n = row & 511;
                    atomicAdd(&g_bnsum[sb * NN + n], rs[mi][rr]);
                    atomicAdd(&g_bnsq [sb * NN + n], rq[mi][rr]);
                }
        }
    }
}

/* ------------- 6) BN finalize + apply + ReLU (fp16 stages) ------------- */
template<bool H16>
__global__ void k_bnapply(const float* __restrict__ g, const float* __restrict__ bb,
                          int sb) {
    int i4 = blockIdx.x * 256 + threadIdx.x;
    float4 v = ((const float4*)g_pre)[i4];
    int r = i4 >> 5;
    int n = r & 511;
    const float invC = 1.f / (float)(MBATCH * HID);
    float mean = g_bnsum[sb * NN + n] * invC;
    float var  = g_bnsq [sb * NN + n] * invC - mean * mean;
    var = fmaxf(var, 0.f);
    float sc = g[n] * rsqrtf(var + EPSV);
    float sh = bb[n] - mean * sc;
    float x0 = fmaxf(v.x * sc + sh, 0.f);
    float x1 = fmaxf(v.y * sc + sh, 0.f);
    float x2 = fmaxf(v.z * sc + sh, 0.f);
    float x3 = fmaxf(v.w * sc + sh, 0.f);
    __half2 p0 = __floats2half2_rn(x0, x1);
    __half2 p1 = __floats2half2_rn(x2, x3);
    uint2 u; u.x = *(unsigned*)&p0; u.y = *(unsigned*)&p1;
    ((uint2*)g_hh)[i4] = u;
    if (H16) {
        float w = g_inv[r];
        __half2 h0 = __floats2half2_rn(w * x0, w * x1);
        __half2 h1 = __floats2half2_rn(w * x2, w * x3);
        uint2 u2; u2.x = *(unsigned*)&h0; u2.y = *(unsigned*)&h1;
        ((uint2*)g_h16)[i4] = u2;
    }
}

/* ---------------- driver ------------------------------------------------ */
extern "C" void kernel_launch(void* const* d_in, const int* in_sizes, int n_in,
                              void* d_out, int out_size) {
    const float* x   = (const float*)d_in[0];
    const float* adj = (const float*)d_in[1];
    const float* ws[3] = {(const float*)d_in[2],  (const float*)d_in[8],  (const float*)d_in[14]};
    const float* bs[3] = {(const float*)d_in[3],  (const float*)d_in[9],  (const float*)d_in[15]};
    const float* we[3] = {(const float*)d_in[4],  (const float*)d_in[10], (const float*)d_in[16]};
    const float* be[3] = {(const float*)d_in[5],  (const float*)d_in[11], (const float*)d_in[17]};
    const float* bg[3] = {(const float*)d_in[6],  (const float*)d_in[12], (const float*)d_in[18]};
    const float* bb[3] = {(const float*)d_in[7],  (const float*)d_in[13], (const float*)d_in[19]};
    const float* w1  = (const float*)d_in[20];
    const float* b1  = (const float*)d_in[21];
    const float* bfg = (const float*)d_in[22];
    const float* bfb = (const float*)d_in[23];
    const float* w2  = (const float*)d_in[24];
    const float* b2  = (const float*)d_in[25];

    (void)in_sizes; (void)n_in; (void)out_size;

    k_csr<<<(MBATCH * ET * NN) / 8, 256>>>(adj);
    k_deg<<<(MBATCH * NN) / 256, 256>>>();
    k_prep2<<<NB_SSUM + NB_STAGE0 + NB_WPREP, 256>>>(
        x, ws[0], we[0], be[0], ws[1], we[1], be[1], ws[2], we[2], be[2], w1, w2);

    /* layer 0 */
    k_agg<IN0><<<ROWS, 128>>>(x, KP0);
    k_gemm<<<ROWS / 128, 256>>>(KP0, bs[0], 0, nullptr, WT0, 0);
    k_bnapply<true><<<ROWS * HID / 4 / 256, 256>>>(bg[0], bb[0], 0);

    /* layer 1 */
    k_agg<HID><<<ROWS, 128>>>((const float*)nullptr, KP12);
    k_gemm<<<ROWS / 128, 256>>>(KP12, bs[1], 0, nullptr, WT1, 1);
    k_bnapply<true><<<ROWS * HID / 4 / 256, 256>>>(bg[1], bb[1], 1);

    /* layer 2 */
    k_agg<HID><<<ROWS, 128>>>((const float*)nullptr, KP12);
    k_gemm<<<ROWS / 128, 256>>>(KP12, bs[2], 0, nullptr, WT2, 2);
    k_bnapply<true><<<ROWS * HID / 4 / 256, 256>>>(bg[2], bb[2], 2);

    /* final MLP */
    k_gemm<<<ROWS / 128, 256>>>(HID, b1, 1, nullptr, WT3, 3);
    k_bnapply<false><<<ROWS * HID / 4 / 256, 256>>>(bfg, bfb, 3);
    k_gemm<<<ROWS / 128, 256>>>(HID, b2, 1, (float*)d_out, WT4, -1);
}

// round 13
// speedup vs baseline: 1.0303x; 1.0303x over previous
#include <cuda_runtime.h>
#include <cuda_fp16.h>

#define MBATCH 32
#define ET 4
#define NN 512
#define IN0 64
#define HID 128
#define ROWS (MBATCH*NN)      /* 16384 */
#define MAXNBR 64
#define KP0 352               /* pad(5*64+4, 32)  */
#define KP12 672              /* pad(5*128+4, 32) */
#define EPSV 1e-5f

/* transposed-weight column offsets inside g_Wt[128][WTCOLS] */
#define WT0 0
#define WT1 352
#define WT2 1024
#define WT3 1696
#define WT4 1824
#define WTCOLS 1952

/* prep2 sub-grid block counts */
#define NB_SSUM   ((MBATCH*ET*NN)/256)            /* 256  */
#define NB_STAGE0 ((MBATCH*NN*IN0/4)/256)         /* 1024 */
#define NB_WPREP  ((HID*WTCOLS + 255)/256)        /* 976  */

/* ---------------- static device scratch (no allocation) ---------------- */
__device__ float          g_inv[MBATCH*NN];
__device__ float          g_ssum[MBATCH*ET*NN];
__device__ __align__(16) unsigned short g_nbr[MBATCH*ET*NN*MAXNBR];  /* node idx */
__device__ int            g_cnt[MBATCH*ET*NN];              // clamped
__device__ int            g_cntfull[MBATCH*ET*NN];          // exact
__device__ __align__(16) __half g_A[ROWS*KP12];             // 22 MB
__device__ __align__(16) __half g_Wt[HID*WTCOLS];           // 0.5 MB
__device__ __align__(16) float  g_pre[ROWS*HID];            // 8.4 MB
__device__ __align__(16) __half g_hh[ROWS*HID];             // post-BN act, fp16
__device__ __align__(16) __half g_h16[ROWS*HID];            // inv-scaled act
__device__ __align__(16) __half g_x16[MBATCH*NN*IN0];       // inv-scaled x
__device__ float          g_bnsum[4*NN];
__device__ float          g_bnsq[4*NN];

/* ------------- 1) CSR build: one warp per (b,e,n) row, float4 reads ----- */
__global__ void k_csr(const float* __restrict__ adj) {
    int row  = blockIdx.x * 8 + (threadIdx.x >> 5);
    int lane = threadIdx.x & 31;
    int n    = row & (NN - 1);
    const float4* p = (const float4*)(adj + (size_t)row * NN);
    unsigned short* out = g_nbr + (size_t)row * MAXNBR;
    int cnt = 0;
    for (int it = 0; it < NN / 128; it++) {
        float4 v = p[it * 32 + lane];
        int mb = (it * 32 + lane) * 4;
        float vc[4] = {v.x, v.y, v.z, v.w};
#pragma unroll
        for (int c = 0; c < 4; c++) {
            bool pr = (vc[c] != 0.f) && (mb + c != n);
            unsigned msk = __ballot_sync(0xffffffffu, pr);
            if (pr) {
                int pos = cnt + __popc(msk & ((1u << lane) - 1u));
                if (pos < MAXNBR) out[pos] = (unsigned short)(mb + c);
            }
            cnt += __popc(msk);
        }
    }
    if (lane == 0) {
        g_cnt[row]     = cnt < MAXNBR ? cnt : MAXNBR;
        g_cntfull[row] = cnt;
    }
}

/* ------------- 2) inv degree from exact counts (adj symmetric, 0/1) ---- */
__global__ void k_deg() {
    int i = blockIdx.x * 256 + threadIdx.x;
    int b = i >> 9, m = i & 511;
    int d = 0;
#pragma unroll
    for (int e = 0; e < ET; e++) d += g_cntfull[((b * ET + e) << 9) + m];
    g_inv[i] = d > 0 ? 1.f / (float)d : 0.f;
}

/* ------------- 3) fused prep: ssum | stage0 | wprep (block dispatch) --- */
__global__ void k_prep2(const float* __restrict__ x,
    const float* __restrict__ ws0, const float* __restrict__ we0, const float* __restrict__ be0,
    const float* __restrict__ ws1, const float* __restrict__ we1, const float* __restrict__ be1,
    const float* __restrict__ ws2, const float* __restrict__ we2, const float* __restrict__ be2,
    const float* __restrict__ w1,  const float* __restrict__ w2) {
    int blk = blockIdx.x;
    if (blk < NB_SSUM) {
        int lidx = blk * 256 + threadIdx.x;
        int b = lidx >> 11;
        int cnt = g_cnt[lidx];
        const unsigned short* nb = g_nbr + (size_t)lidx * MAXNBR;
        const float* invb = g_inv + b * NN;
        float s = 0.f;
        for (int i = 0; i < cnt; i++) s += invb[nb[i]];
        g_ssum[lidx] = s;
        if (lidx < 4 * NN) { g_bnsum[lidx] = 0.f; g_bnsq[lidx] = 0.f; }
        return;
    }
    blk -= NB_SSUM;
    if (blk < NB_STAGE0) {
        int i4 = blk * 256 + threadIdx.x;
        float4 v = ((const float4*)x)[i4];
        int r = i4 >> 4;
        float w = g_inv[r];
        __half2 h0 = __floats2half2_rn(w * v.x, w * v.y);
        __half2 h1 = __floats2half2_rn(w * v.z, w * v.w);
        uint2 u; u.x = *(unsigned*)&h0; u.y = *(unsigned*)&h1;
        ((uint2*)g_x16)[i4] = u;
        return;
    }
    blk -= NB_STAGE0;
    {
        int idx = blk * 256 + threadIdx.x;
        if (idx >= HID * WTCOLS) return;
        int o = idx / WTCOLS, k = idx - o * WTCOLS;
        float v = 0.f;
        if (k < WT1) {
            int kk = k;
            if (kk < 64)       v = ws0[kk * HID + o];
            else if (kk < 320) { int e = (kk - 64) >> 6, j = (kk - 64) & 63;
                                 v = we0[j * (HID * ET) + o * ET + e]; }
            else if (kk < 324)   v = be0[o * ET + (kk - 320)];
        } else if (k < WT2) {
            int kk = k - WT1;
            if (kk < 128)      v = ws1[kk * HID + o];
            else if (kk < 640) { int e = (kk - 128) >> 7, j = (kk - 128) & 127;
                                 v = we1[j * (HID * ET) + o * ET + e]; }
            else if (kk < 644)   v = be1[o * ET + (kk - 640)];
        } else if (k < WT3) {
            int kk = k - WT2;
            if (kk < 128)      v = ws2[kk * HID + o];
            else if (kk < 640) { int e = (kk - 128) >> 7, j = (kk - 128) & 127;
                                 v = we2[j * (HID * ET) + o * ET + e]; }
            else if (kk < 644)   v = be2[o * ET + (kk - 640)];
        } else if (k < WT4) {
            v = w1[(k - WT3) * HID + o];
        } else {
            v = w2[(k - WT4) * HID + o];
        }
        g_Wt[o * WTCOLS + k] = __float2half_rn(v);
    }
}

/* ------------- 4) sparse aggregation: u16 idx + fp16 tree-sum ---------- */
/* __launch_bounds__(128, 16): 16*128 = 2048 thr/SM -> hard 32-reg cap,   */
/* 100%% theoretical occupancy. One-variable experiment vs R12 (40 regs). */
template<int IN>
__global__ void __launch_bounds__(128, 16) k_agg(const float* __restrict__ x0, int KP) {
    constexpr int VEC = IN / 32;   // 4 for IN=128, 2 for IN=64
    const __half* __restrict__ h16 = (IN == IN0) ? (const __half*)g_x16
                                                 : (const __half*)g_h16;
    int r = blockIdx.x, b = r >> 9, n = r & 511;
    int warp = threadIdx.x >> 5, lane = threadIdx.x & 31;
    __half* Arow = g_A + (size_t)r * KP;

    if (warp == 0) {   /* self-feature copy */
        if (IN == IN0) {
            float2 v = *(const float2*)(x0 + (size_t)r * IN + lane * 2);
            *(__half2*)(Arow + lane * 2) = __floats2half2_rn(v.x, v.y);
        } else {
            *(uint2*)(Arow + lane * 4) =
                *(const uint2*)((const __half*)g_hh + (size_t)r * IN + lane * 4);
        }
    }
    if (warp == 1) {   /* s-values + zero-pad tail */
        if (lane < ET)
            Arow[5 * IN + lane] = __float2half_rn(g_ssum[((b * ET + lane) << 9) + n]);
        for (int k = 5 * IN + 4 + lane; k < KP; k += 32) Arow[k] = __half(0.f);
    }

    int e = warp;
    int lidx = ((b * ET + e) << 9) + n;
    int cnt = g_cnt[lidx];
    const unsigned short* nb = g_nbr + (size_t)lidx * MAXNBR;
    const uint2* nbq = (const uint2*)nb;      /* 16 groups of 4 u16 */
    const __half* hb = h16 + (size_t)b * NN * IN + lane * VEC;

    float acc[VEC];
#pragma unroll
    for (int c = 0; c < VEC; c++) acc[c] = 0.f;

    int i = 0;
    if (cnt >= 4) {
        uint2 qc = nbq[0];                    /* index prefetch, distance 1 */
        for (; i + 4 <= cnt; i += 4) {
            int g = (i >> 2) + 1;
            uint2 qn = nbq[g < 16 ? g : 15];
            int m0 = qc.x & 0xffff, m1 = qc.x >> 16;
            int m2 = qc.y & 0xffff, m3 = qc.y >> 16;
            if (VEC == 4) {
                uint2 f0 = *(const uint2*)(hb + (size_t)m0 * IN);
                uint2 f1 = *(const uint2*)(hb + (size_t)m1 * IN);
                uint2 f2 = *(const uint2*)(hb + (size_t)m2 * IN);
                uint2 f3 = *(const uint2*)(hb + (size_t)m3 * IN);
                /* fp16 depth-2 tree per half2 column, one convert per batch */
                __half2 sx = __hadd2(__hadd2(*(__half2*)&f0.x, *(__half2*)&f1.x),
                                     __hadd2(*(__half2*)&f2.x, *(__half2*)&f3.x));
                __half2 sy = __hadd2(__hadd2(*(__half2*)&f0.y, *(__half2*)&f1.y),
                                     __hadd2(*(__half2*)&f2.y, *(__half2*)&f3.y));
                float2 a = __half22float2(sx);
                float2 bb2 = __half22float2(sy);
                acc[0] += a.x; acc[1] += a.y; acc[2] += bb2.x; acc[3] += bb2.y;
            } else {
                unsigned f0 = *(const unsigned*)(hb + (size_t)m0 * IN);
                unsigned f1 = *(const unsigned*)(hb + (size_t)m1 * IN);
                unsigned f2 = *(const unsigned*)(hb + (size_t)m2 * IN);
                unsigned f3 = *(const unsigned*)(hb + (size_t)m3 * IN);
                __half2 s = __hadd2(__hadd2(*(__half2*)&f0, *(__half2*)&f1),
                                    __hadd2(*(__half2*)&f2, *(__half2*)&f3));
                float2 a = __half22float2(s);
                acc[0] += a.x; acc[1] += a.y;
            }
            qc = qn;
        }
    }
    for (; i < cnt; i++) {
        int m = nb[i];
        if (VEC == 4) {
            uint2 f0 = *(const uint2*)(hb + (size_t)m * IN);
            float2 a = __half22float2(*(__half2*)&f0.x);
            float2 bb2 = __half22float2(*(__half2*)&f0.y);
            acc[0] += a.x; acc[1] += a.y; acc[2] += bb2.x; acc[3] += bb2.y;
        } else {
            unsigned f0 = *(const unsigned*)(hb + (size_t)m * IN);
            float2 a = __half22float2(*(__half2*)&f0);
            acc[0] += a.x; acc[1] += a.y;
        }
    }

    if (VEC == 4) {
        __half2 o0 = __floats2half2_rn(acc[0], acc[1]);
        __half2 o1 = __floats2half2_rn(acc[2], acc[3]);
        uint2 u; u.x = *(unsigned*)&o0; u.y = *(unsigned*)&o1;
        *(uint2*)(Arow + IN + e * IN + lane * 4) = u;
    } else {
        *(__half2*)(Arow + IN + e * IN + lane * 2) = __floats2half2_rn(acc[0], acc[1]);
    }
}

/* ------------- 5) FP16 tensor GEMM (m16n8k16, ldmatrix) + BN stats ----- */
#define SROW 40   /* smem row pitch in halfs (32 data + 8 pad) */

__device__ __forceinline__ unsigned smaddr(const void* p) {
    return (unsigned)__cvta_generic_to_shared(p);
}
__device__ __forceinline__ void cpasync16(unsigned s, const void* g) {
    asm volatile("cp.async.cg.shared.global [%0], [%1], 16;\n" :: "r"(s), "l"(g));
}
__device__ __forceinline__ void ldsm4(unsigned& r0, unsigned& r1, unsigned& r2,
                                      unsigned& r3, unsigned addr) {
    asm volatile("ldmatrix.sync.aligned.m8n8.x4.shared.b16 {%0,%1,%2,%3}, [%4];\n"
                 : "=r"(r0), "=r"(r1), "=r"(r2), "=r"(r3) : "r"(addr));
}

__global__ void __launch_bounds__(256) k_gemm(int KP, const float* __restrict__ bias,
                                              int srcH, float* __restrict__ Cout,
                                              int wofs, int sb) {
    const __half* A = srcH ? (const __half*)g_hh : (const __half*)g_A;
    float* C = Cout ? Cout : (float*)g_pre;

    __shared__ __half sA[2][128 * SROW];
    __shared__ __half sB[2][128 * SROW];
    const unsigned BUFB = 128 * SROW * 2;        /* bytes per buffer */

    int tid = threadIdx.x;
    int lane = tid & 31, warp = tid >> 5;
    int wm = (warp >> 1) * 32, wn = (warp & 1) * 64;
    int grp = lane >> 2, qid = lane & 3;
    int rowbase = blockIdx.x * 128;
    int KB = KP >> 5;

    unsigned aBase = smaddr(&sA[0][0]);
    unsigned bBase = smaddr(&sB[0][0]);
    int l7 = lane & 7, lb3 = (lane >> 3) & 1, lb4 = lane >> 4;
    unsigned aOff[2], bOff[4];
#pragma unroll
    for (int mi = 0; mi < 2; mi++)
        aOff[mi] = ((wm + mi * 16 + lb3 * 8 + l7) * SROW + lb4 * 8) * 2;
#pragma unroll
    for (int p = 0; p < 4; p++)
        bOff[p] = ((wn + p * 16 + lb4 * 8 + l7) * SROW + lb3 * 8) * 2;

    float acc[2][8][4];
#pragma unroll
    for (int a = 0; a < 2; a++)
#pragma unroll
        for (int bq = 0; bq < 8; bq++)
#pragma unroll
            for (int c = 0; c < 4; c++) acc[a][bq][c] = 0.f;

    auto issue = [&](int kb, int buf) {
        int kof = kb * 32;
#pragma unroll
        for (int i = 0; i < 2; i++) {
            int c = tid + i * 256, row = c >> 2, q = c & 3;
            cpasync16(smaddr(&sA[buf][row * SROW + q * 8]),
                      A + (size_t)(rowbase + row) * KP + kof + q * 8);
            cpasync16(smaddr(&sB[buf][row * SROW + q * 8]),
                      (const __half*)g_Wt + (size_t)row * WTCOLS + wofs + kof + q * 8);
        }
        asm volatile("cp.async.commit_group;\n" ::);
    };

    issue(0, 0);
    for (int kb = 0; kb < KB; kb++) {
        int buf = kb & 1;
        if (kb + 1 < KB) {
            issue(kb + 1, buf ^ 1);
            asm volatile("cp.async.wait_group 1;\n" ::);
        } else {
            asm volatile("cp.async.wait_group 0;\n" ::);
        }
        __syncthreads();

#pragma unroll
        for (int ks = 0; ks < 2; ks++) {
            unsigned kby = ks * 32 + buf * BUFB;
            unsigned bf[8][2];
#pragma unroll
            for (int p = 0; p < 4; p++)
                ldsm4(bf[2*p][0], bf[2*p][1], bf[2*p+1][0], bf[2*p+1][1],
                      bBase + bOff[p] + kby);
#pragma unroll
            for (int mi = 0; mi < 2; mi++) {
                unsigned a0, a1, a2, a3;
                ldsm4(a0, a1, a2, a3, aBase + aOff[mi] + kby);
#pragma unroll
                for (int ni = 0; ni < 8; ni++) {
                    asm volatile(
                        "mma.sync.aligned.m16n8k16.row.col.f32.f16.f16.f32 "
                        "{%0,%1,%2,%3}, {%4,%5,%6,%7}, {%8,%9}, {%0,%1,%2,%3};\n"
                        : "+f"(acc[mi][ni][0]), "+f"(acc[mi][ni][1]),
                          "+f"(acc[mi][ni][2]), "+f"(acc[mi][ni][3])
                        : "r"(a0), "r"(a1), "r"(a2), "r"(a3),
                          "r"(bf[ni][0]), "r"(bf[ni][1]));
                }
            }
        }
        __syncthreads();
    }

    /* epilogue: +bias, store, per-row BN partial sums */
    float rs[2][2] = {{0.f,0.f},{0.f,0.f}};
    float rq[2][2] = {{0.f,0.f},{0.f,0.f}};
#pragma unroll
    for (int mi = 0; mi < 2; mi++) {
        int row = rowbase + wm + mi * 16 + grp;
#pragma unroll
        for (int ni = 0; ni < 8; ni++) {
            int col = wn + ni * 8 + qid * 2;
            float b0 = bias[col], b1 = bias[col + 1];
            float v0 = acc[mi][ni][0] + b0, v1 = acc[mi][ni][1] + b1;
            float v2 = acc[mi][ni][2] + b0, v3 = acc[mi][ni][3] + b1;
            C[(size_t)row * HID + col]           = v0;
            C[(size_t)row * HID + col + 1]       = v1;
            C[(size_t)(row + 8) * HID + col]     = v2;
            C[(size_t)(row + 8) * HID + col + 1] = v3;
            rs[mi][0] += v0 + v1; rq[mi][0] += v0 * v0 + v1 * v1;
            rs[mi][1] += v2 + v3; rq[mi][1] += v2 * v2 + v3 * v3;
        }
    }
    if (sb >= 0) {
#pragma unroll
        for (int mi = 0; mi < 2; mi++)
#pragma unroll
            for (int rr = 0; rr < 2; rr++) {
                rs[mi][rr] += __shfl_xor_sync(0xffffffffu, rs[mi][rr], 1);
                rs[mi][rr] += __shfl_xor_sync(0xffffffffu, rs[mi][rr], 2);
                rq[mi][rr] += __shfl_xor_sync(0xffffffffu, rq[mi][rr], 1);
                rq[mi][rr] += __shfl_xor_sync(0xffffffffu, rq[mi][rr], 2);
            }
        if (qid == 0) {
#pragma unroll
            for (int mi = 0; mi < 2; mi++)
#pragma unroll
                for (int rr = 0; rr < 2; rr++) {
                    int row = rowbase + wm + mi * 16 + grp + rr * 8;
                    int n = row & 511;
                    atomicAdd(&g_bnsum[sb * NN + n], rs[mi][rr]);
                    atomicAdd(&g_bnsq [sb * NN + n], rq[mi][rr]);
                }
        }
    }
}

/* ------------- 6) BN finalize + apply + ReLU (fp16 stages) ------------- */
template<bool H16>
__global__ void k_bnapply(const float* __restrict__ g, const float* __restrict__ bb,
                          int sb) {
    int i4 = blockIdx.x * 256 + threadIdx.x;
    float4 v = ((const float4*)g_pre)[i4];
    int r = i4 >> 5;
    int n = r & 511;
    const float invC = 1.f / (float)(MBATCH * HID);
    float mean = g_bnsum[sb * NN + n] * invC;
    float var  = g_bnsq [sb * NN + n] * invC - mean * mean;
    var = fmaxf(var, 0.f);
    float sc = g[n] * rsqrtf(var + EPSV);
    float sh = bb[n] - mean * sc;
    float x0 = fmaxf(v.x * sc + sh, 0.f);
    float x1 = fmaxf(v.y * sc + sh, 0.f);
    float x2 = fmaxf(v.z * sc + sh, 0.f);
    float x3 = fmaxf(v.w * sc + sh, 0.f);
    __half2 p0 = __floats2half2_rn(x0, x1);
    __half2 p1 = __floats2half2_rn(x2, x3);
    uint2 u; u.x = *(unsigned*)&p0; u.y = *(unsigned*)&p1;
    ((uint2*)g_hh)[i4] = u;
    if (H16) {
        float w = g_inv[r];
        __half2 h0 = __floats2half2_rn(w * x0, w * x1);
        __half2 h1 = __floats2half2_rn(w * x2, w * x3);
        uint2 u2; u2.x = *(unsigned*)&h0; u2.y = *(unsigned*)&h1;
        ((uint2*)g_h16)[i4] = u2;
    }
}

/* ---------------- driver ------------------------------------------------ */
extern "C" void kernel_launch(void* const* d_in, const int* in_sizes, int n_in,
                              void* d_out, int out_size) {
    const float* x   = (const float*)d_in[0];
    const float* adj = (const float*)d_in[1];
    const float* ws[3] = {(const float*)d_in[2],  (const float*)d_in[8],  (const float*)d_in[14]};
    const float* bs[3] = {(const float*)d_in[3],  (const float*)d_in[9],  (const float*)d_in[15]};
    const float* we[3] = {(const float*)d_in[4],  (const float*)d_in[10], (const float*)d_in[16]};
    const float* be[3] = {(const float*)d_in[5],  (const float*)d_in[11], (const float*)d_in[17]};
    const float* bg[3] = {(const float*)d_in[6],  (const float*)d_in[12], (const float*)d_in[18]};
    const float* bb[3] = {(const float*)d_in[7],  (const float*)d_in[13], (const float*)d_in[19]};
    const float* w1  = (const float*)d_in[20];
    const float* b1  = (const float*)d_in[21];
    const float* bfg = (const float*)d_in[22];
    const float* bfb = (const float*)d_in[23];
    const float* w2  = (const float*)d_in[24];
    const float* b2  = (const float*)d_in[25];

    (void)in_sizes; (void)n_in; (void)out_size;

    k_csr<<<(MBATCH * ET * NN) / 8, 256>>>(adj);
    k_deg<<<(MBATCH * NN) / 256, 256>>>();
    k_prep2<<<NB_SSUM + NB_STAGE0 + NB_WPREP, 256>>>(
        x, ws[0], we[0], be[0], ws[1], we[1], be[1], ws[2], we[2], be[2], w1, w2);

    /* layer 0 */
    k_agg<IN0><<<ROWS, 128>>>(x, KP0);
    k_gemm<<<ROWS / 128, 256>>>(KP0, bs[0], 0, nullptr, WT0, 0);
    k_bnapply<true><<<ROWS * HID / 4 / 256, 256>>>(bg[0], bb[0], 0);

    /* layer 1 */
    k_agg<HID><<<ROWS, 128>>>((const float*)nullptr, KP12);
    k_gemm<<<ROWS / 128, 256>>>(KP12, bs[1], 0, nullptr, WT1, 1);
    k_bnapply<true><<<ROWS * HID / 4 / 256, 256>>>(bg[1], bb[1], 1);

    /* layer 2 */
    k_agg<HID><<<ROWS, 128>>>((const float*)nullptr, KP12);
    k_gemm<<<ROWS / 128, 256>>>(KP12, bs[2], 0, nullptr, WT2, 2);
    k_bnapply<true><<<ROWS * HID / 4 / 256, 256>>>(bg[2], bb[2], 2);

    /* final MLP */
    k_gemm<<<ROWS / 128, 256>>>(HID, b1, 1, nullptr, WT3, 3);
    k_bnapply<false><<<ROWS * HID / 4 / 256, 256>>>(bfg, bfb, 3);
    k_gemm<<<ROWS / 128, 256>>>(HID, b2, 1, (float*)d_out, WT4, -1);
}